// round 8
// baseline (speedup 1.0000x reference)
#include <cuda_runtime.h>
#include <cstddef>

#define T_  512
#define B_  64
#define H_  512
#define G3  1536   // 3*H

// ---------------- device scratch ----------------
__device__ float g_gi[(size_t)T_ * B_ * G3];
__device__ float g_y0[(size_t)T_ * B_ * H_];
__device__ float g_h[B_ * H_];
__device__ float g_ghp[4 * B_ * G3];
__device__ float g_dummy[B_ * H_];
__device__ volatile unsigned g_flags[96 * 32];   // one padded flag per CTA (128B apart)

#define NB_REC 96

// packed fp32x2 FMA (bit-exact 2x FFMA)
__device__ __forceinline__ void ffma2(unsigned long long& d,
                                      unsigned long long a,
                                      unsigned long long b) {
    asm("fma.rn.f32x2 %0, %1, %2, %0;" : "+l"(d) : "l"(a), "l"(b));
}

__device__ __forceinline__ float acc_sum(unsigned long long v) {
    float2 f;
    asm("mov.b64 {%0, %1}, %2;" : "=f"(f.x), "=f"(f.y) : "l"(v));
    return f.x + f.y;
}

// ---------------- flag-based grid barrier (96 co-resident CTAs) ----------------
// v is monotonically increasing within a launch; flags zeroed by k_seth per launch.
__device__ __forceinline__ void gridbar(unsigned v) {
    __syncthreads();
    if (threadIdx.x == 0) {
        __threadfence();                       // release all prior CTA writes
        g_flags[blockIdx.x * 32] = v;
    }
    if (threadIdx.x < NB_REC) {
        while (g_flags[threadIdx.x * 32] < v) { }
        __threadfence();                       // acquire
    }
    __syncthreads();
}

// ---------------- init hidden state + reset barrier flags ----------------
__global__ void k_seth(const float* __restrict__ h0) {
    int i = blockIdx.x * blockDim.x + threadIdx.x;
    g_h[i] = h0[i];
    if (i < 96 * 32) g_flags[i] = 0u;
}

// ---------------- input projection GEMM: 128x128 tile, 8x8 micro, f32x2 ----------------
// g_gi[m][n] = X[m][:].W[n][:] + bias[n];  M=32768, N=1536, K=512
#define GS 34   // 32 + 2 pad: stride 34 words -> conflict-free strided-16 LDS.64
__global__ void __launch_bounds__(256, 1) k_gemm_in(
    const float* __restrict__ Xe, int x_internal,
    const float* __restrict__ W, const float* __restrict__ bias)
{
    __shared__ float xs[128 * GS];
    __shared__ float ws[128 * GS];
    const float* X = x_internal ? g_y0 : Xe;

    const int n0 = blockIdx.x * 128;
    const int m0 = blockIdx.y * 128;
    const int tid = threadIdx.x;
    const int tx = tid & 15, ty = tid >> 4;

    unsigned long long acc[8][8];
#pragma unroll
    for (int i = 0; i < 8; i++)
#pragma unroll
        for (int j = 0; j < 8; j++) acc[i][j] = 0ull;

    const float* Xp = X + (size_t)m0 * 512;
    const float* Wp = W + (size_t)n0 * 512;

    int aoff[8], woff[8];
#pragma unroll
    for (int i = 0; i < 8; i++) aoff[i] = (ty + 16 * i) * GS;
#pragma unroll
    for (int j = 0; j < 8; j++) woff[j] = (tx + 16 * j) * GS;

    for (int kb = 0; kb < 512; kb += 32) {
        // stage: 128 rows x 32 k; each thread 4 float4 per tile (as 2x ull stores)
#pragma unroll
        for (int r = 0; r < 4; r++) {
            int idx = tid + r * 256;
            int row = idx >> 3, f4 = (idx & 7) * 4;
            ulonglong2 xv = *reinterpret_cast<const ulonglong2*>(
                &Xp[(size_t)row * 512 + kb + f4]);
            ulonglong2 wv = *reinterpret_cast<const ulonglong2*>(
                &Wp[(size_t)row * 512 + kb + f4]);
            int base = row * GS + f4;
            *reinterpret_cast<unsigned long long*>(&xs[base])     = xv.x;
            *reinterpret_cast<unsigned long long*>(&xs[base + 2]) = xv.y;
            *reinterpret_cast<unsigned long long*>(&ws[base])     = wv.x;
            *reinterpret_cast<unsigned long long*>(&ws[base + 2]) = wv.y;
        }
        __syncthreads();

#pragma unroll 4
        for (int k2 = 0; k2 < 16; k2++) {
            unsigned long long a[8], w[8];
#pragma unroll
            for (int i = 0; i < 8; i++)
                a[i] = *reinterpret_cast<const unsigned long long*>(&xs[aoff[i] + 2 * k2]);
#pragma unroll
            for (int j = 0; j < 8; j++)
                w[j] = *reinterpret_cast<const unsigned long long*>(&ws[woff[j] + 2 * k2]);
#pragma unroll
            for (int i = 0; i < 8; i++)
#pragma unroll
                for (int j = 0; j < 8; j++)
                    ffma2(acc[i][j], a[i], w[j]);
        }
        __syncthreads();
    }

#pragma unroll
    for (int i = 0; i < 8; i++) {
        int m = m0 + ty + 16 * i;
#pragma unroll
        for (int j = 0; j < 8; j++) {
            int n = n0 + tx + 16 * j;
            g_gi[(size_t)m * G3 + n] = acc_sum(acc[i][j]) + bias[n];
        }
    }
}

// ---------------- persistent recurrence kernel ----------------
// 96 CTAs = 24 n-tiles x 4 k-chunks; 256 threads.
// Phase 1: 64x64x128 gh partial (4x4 micro, f32x2). Phase 2: warp-per-gate.
#define RS 132   // 128 + 4 pad
__global__ void __launch_bounds__(256, 1) k_rec(
    const float* __restrict__ Whh, const float* __restrict__ bhh,
    const float* __restrict__ lng, const float* __restrict__ lnb,
    float* __restrict__ y_ext, int y_internal, float* __restrict__ hlast)
{
    extern __shared__ float sm[];
    float* wsm = sm;             // [64*RS] Whh tile, cached across all steps
    float* hs  = sm + 64 * RS;   // [64*RS] h tile; reused as gate smem in phase 2

    const int tid = threadIdx.x;
    const int bx  = blockIdx.x;
    const int nt  = bx % 24;
    const int kc  = bx / 24;
    const int n0  = nt * 64;
    const int k0  = kc * 128;
    float* y = y_internal ? g_y0 : y_ext;

    // stage Whh tile once: wsm[n][kk]
#pragma unroll
    for (int r = 0; r < 8; r++) {
        int idx = tid + r * 256;
        int n = idx >> 5, kf4 = (idx & 31) * 4;
        *reinterpret_cast<float4*>(&wsm[n * RS + kf4]) =
            *reinterpret_cast<const float4*>(&Whh[(size_t)(n0 + n) * 512 + k0 + kf4]);
    }

    const int tx = tid & 15, ty = tid >> 4;
    int aoff[4], woff[4];
#pragma unroll
    for (int i = 0; i < 4; i++) aoff[i] = (ty + 16 * i) * RS;
#pragma unroll
    for (int j = 0; j < 4; j++) woff[j] = (tx + 16 * j) * RS;

    const int w    = tid >> 5;
    const int lane = tid & 31;

    for (int t = 0; t < T_; t++) {
        __syncthreads();
        // stage h tile: hs[b][kk]
#pragma unroll
        for (int r = 0; r < 8; r++) {
            int idx = tid + r * 256;
            int b = idx >> 5, kf4 = (idx & 31) * 4;
            *reinterpret_cast<float4*>(&hs[b * RS + kf4]) =
                *reinterpret_cast<const float4*>(&g_h[b * 512 + k0 + kf4]);
        }
        __syncthreads();

        unsigned long long acc[4][4];
#pragma unroll
        for (int i = 0; i < 4; i++)
#pragma unroll
            for (int j = 0; j < 4; j++) acc[i][j] = 0ull;

#pragma unroll 8
        for (int k4 = 0; k4 < 128; k4 += 4) {
            ulonglong2 av[4], wv[4];
#pragma unroll
            for (int i = 0; i < 4; i++)
                av[i] = *reinterpret_cast<const ulonglong2*>(&hs[aoff[i] + k4]);
#pragma unroll
            for (int j = 0; j < 4; j++)
                wv[j] = *reinterpret_cast<const ulonglong2*>(&wsm[woff[j] + k4]);
#pragma unroll
            for (int i = 0; i < 4; i++)
#pragma unroll
                for (int j = 0; j < 4; j++) {
                    ffma2(acc[i][j], av[i].x, wv[j].x);
                    ffma2(acc[i][j], av[i].y, wv[j].y);
                }
        }

#pragma unroll
        for (int i = 0; i < 4; i++) {
            int b = ty + 16 * i;
#pragma unroll
            for (int j = 0; j < 4; j++)
                g_ghp[(size_t)(kc * 64 + b) * G3 + (n0 + tx + 16 * j)] =
                    acc_sum(acc[i][j]);
        }

        gridbar(2 * (unsigned)t + 1u);

        // ---------- phase 2: warp-per-gate, CTA b = bx < 64 ----------
        if (bx < B_) {
            const int b = bx;
            const float* git = g_gi + ((size_t)t * B_ + b) * G3;

            if (w < 3) {
                const int gbase = w * 512;
                float v[16], gin[16];
                // load + k-split reduce: j = lane + 32q
#pragma unroll
                for (int q = 0; q < 16; q++) {
                    int j = lane + 32 * q;
                    int col = gbase + j;
                    float s = bhh[col];
                    s += g_ghp[(size_t)(0 * 64 + b) * G3 + col];
                    s += g_ghp[(size_t)(1 * 64 + b) * G3 + col];
                    s += g_ghp[(size_t)(2 * 64 + b) * G3 + col];
                    s += g_ghp[(size_t)(3 * 64 + b) * G3 + col];
                    float gi = git[col];
                    if (w < 2) { v[q] = gi + s; gin[q] = 0.f; }
                    else       { v[q] = s;      gin[q] = gi; }
                }

                if (w < 2) {
                    // LN + sigmoid for r (w=0) or i (w=1), write gate to smem
                    float s1 = 0.f, s2 = 0.f;
#pragma unroll
                    for (int q = 0; q < 16; q++) { s1 += v[q]; s2 += v[q] * v[q]; }
#pragma unroll
                    for (int o = 16; o; o >>= 1) {
                        s1 += __shfl_xor_sync(0xffffffffu, s1, o);
                        s2 += __shfl_xor_sync(0xffffffffu, s2, o);
                    }
                    float mu = s1 * (1.0f / 512.0f);
                    float rs = rsqrtf(s2 * (1.0f / 512.0f) - mu * mu + 1e-5f);
#pragma unroll
                    for (int q = 0; q < 16; q++) {
                        int j = lane + 32 * q;
                        int col = gbase + j;
                        float x = (v[q] - mu) * rs * lng[col] + lnb[col];
                        hs[col] = 1.0f / (1.0f + __expf(-x));
                    }
                    asm volatile("bar.sync 1, 96;" ::: "memory");
                } else {
                    // n gate: needs resetgate from warp 0
                    asm volatile("bar.sync 1, 96;" ::: "memory");
#pragma unroll
                    for (int q = 0; q < 16; q++) {
                        int j = lane + 32 * q;
                        v[q] = gin[q] + hs[j] * v[q];   // gi_n + rg * gh_n
                    }
                    float s1 = 0.f, s2 = 0.f;
#pragma unroll
                    for (int q = 0; q < 16; q++) { s1 += v[q]; s2 += v[q] * v[q]; }
#pragma unroll
                    for (int o = 16; o; o >>= 1) {
                        s1 += __shfl_xor_sync(0xffffffffu, s1, o);
                        s2 += __shfl_xor_sync(0xffffffffu, s2, o);
                    }
                    float mu = s1 * (1.0f / 512.0f);
                    float rs = rsqrtf(s2 * (1.0f / 512.0f) - mu * mu + 1e-5f);
#pragma unroll
                    for (int q = 0; q < 16; q++) {
                        int j = lane + 32 * q;
                        int col = 1024 + j;
                        float x = (v[q] - mu) * rs * lng[col] + lnb[col];
                        float ng = tanhf(x);
                        float ig = hs[512 + j];
                        float hold = g_h[b * 512 + j];
                        float hy = ng + ig * (hold - ng);
                        g_h[b * 512 + j] = hy;
                        y[((size_t)t * B_ + b) * H_ + j] = hy;
                        if (t == T_ - 1) hlast[b * 512 + j] = hy;
                    }
                }
            } else if (w == 3 && t + 1 < T_) {
                // L2 prefetch of next step's gi row (two 128B-line touches/lane)
                float s = 0.f;
                const float* gnext = g_gi + ((size_t)(t + 1) * B_ + b) * G3;
#pragma unroll
                for (int q = 0; q < 2; q++) {
                    int line = lane + 32 * q;
                    if (line < 48) s += gnext[line * 32];
                }
                hs[1100 + lane] = s;  // sink (unused region, no reader)
            }
        }

        gridbar(2 * (unsigned)t + 2u);
    }
}

// ---------------- launcher ----------------
extern "C" void kernel_launch(void* const* d_in, const int* in_sizes, int n_in,
                              void* d_out, int out_size) {
    (void)in_sizes; (void)n_in;
    const float* x   = (const float*)d_in[0];
    const float* h0  = (const float*)d_in[1];
    const float* Wih = (const float*)d_in[2];
    const float* bih = (const float*)d_in[3];
    const float* Whh = (const float*)d_in[4];
    const float* bhh = (const float*)d_in[5];
    const float* lng = (const float*)d_in[6];
    const float* lnb = (const float*)d_in[7];
    float* out = (float*)d_out;

    const size_t TBH = (size_t)T_ * B_ * H_;
    const size_t LBH = (size_t)2 * B_ * H_;
    bool has_hl = ((size_t)out_size >= TBH + LBH);

    float* hl_dummy = nullptr;
    cudaGetSymbolAddress((void**)&hl_dummy, g_dummy);
    float* hl0 = has_hl ? out + TBH           : hl_dummy;
    float* hl1 = has_hl ? out + TBH + B_ * H_ : hl_dummy;

    const int smem_rec = 2 * 64 * RS * (int)sizeof(float);  // 67,584 B
    cudaFuncSetAttribute(k_rec, cudaFuncAttributeMaxDynamicSharedMemorySize, smem_rec);

    dim3 gg(G3 / 128, (T_ * B_) / 128);  // (12, 256)

    // layer 0
    k_gemm_in<<<gg, 256>>>(x, 0, Wih, bih);
    k_seth<<<(B_ * H_) / 256, 256>>>(h0);
    k_rec<<<NB_REC, 256, smem_rec>>>(Whh, bhh, lng, lnb, out, 1, hl0);

    // layer 1
    k_gemm_in<<<gg, 256>>>(nullptr, 1, Wih + (size_t)G3 * H_, bih + G3);
    k_seth<<<(B_ * H_) / 256, 256>>>(h0 + B_ * H_);
    k_rec<<<NB_REC, 256, smem_rec>>>(Whh + (size_t)G3 * H_, bhh + G3,
                                     lng + G3, lnb + G3,
                                     out, 0, hl1);
}

// round 9
// speedup vs baseline: 1.1939x; 1.1939x over previous
#include <cuda_runtime.h>
#include <cstddef>

#define T_  512
#define B_  64
#define H_  512
#define G3  1536   // 3*H

// ---------------- device scratch ----------------
__device__ float g_gi[(size_t)T_ * B_ * G3];
__device__ float g_y0[(size_t)T_ * B_ * H_];
__device__ float g_h[B_ * H_];
__device__ float g_ghp[4 * B_ * G3];
__device__ float g_dummy[B_ * H_];
__device__ volatile unsigned g_flags[96 * 32];   // one flag per CTA, 128B apart

#define NB_REC 96

// packed fp32x2 FMA (bit-exact 2x FFMA)
__device__ __forceinline__ void ffma2(unsigned long long& d,
                                      unsigned long long a,
                                      unsigned long long b) {
    asm("fma.rn.f32x2 %0, %1, %2, %0;" : "+l"(d) : "l"(a), "l"(b));
}

__device__ __forceinline__ float acc_sum(unsigned long long v) {
    float2 f;
    asm("mov.b64 {%0, %1}, %2;" : "=f"(f.x), "=f"(f.y) : "l"(v));
    return f.x + f.y;
}

// ---------------- flag barrier: no atomic chain, 32 pollers w/ backoff ------
__device__ __forceinline__ void gridbar(unsigned v) {
    __threadfence();           // every thread releases its own prior writes
    __syncthreads();
    if (threadIdx.x == 0) g_flags[blockIdx.x * 32] = v;
    if (threadIdx.x < 32) {
        bool done = false;
        while (!done) {
            done = true;
#pragma unroll
            for (int q = 0; q < 3; q++)
                done &= (g_flags[(threadIdx.x + 32 * q) * 32] >= v);
            if (!done) __nanosleep(50);
        }
        __threadfence();       // acquire
    }
    __syncthreads();
}

// ---------------- dual block reduction over 256 threads ----------------
__device__ __forceinline__ void blockReduce2(float& a, float& b, float* red) {
    int tid = threadIdx.x, lane = tid & 31, wid = tid >> 5;
#pragma unroll
    for (int o = 16; o; o >>= 1) {
        a += __shfl_down_sync(0xffffffffu, a, o);
        b += __shfl_down_sync(0xffffffffu, b, o);
    }
    if (lane == 0) { red[wid] = a; red[8 + wid] = b; }
    __syncthreads();
    if (tid < 32) {
        a = (lane < 8) ? red[lane] : 0.0f;
        b = (lane < 8) ? red[8 + lane] : 0.0f;
#pragma unroll
        for (int o = 4; o; o >>= 1) {
            a += __shfl_down_sync(0xffffffffu, a, o);
            b += __shfl_down_sync(0xffffffffu, b, o);
        }
        if (lane == 0) { red[16] = a; red[17] = b; }
    }
    __syncthreads();
    a = red[16]; b = red[17];
    __syncthreads();
}

// ---------------- init hidden state + reset barrier flags ----------------
__global__ void k_seth(const float* __restrict__ h0) {
    int i = blockIdx.x * blockDim.x + threadIdx.x;
    g_h[i] = h0[i];
    if (i < 96 * 32) g_flags[i] = 0u;
}

// ---------------- input projection GEMM: 128x128 tile, 8x8 micro, f32x2 -----
#define GS 34   // 32 + 2 pad
__global__ void __launch_bounds__(256, 1) k_gemm_in(
    const float* __restrict__ Xe, int x_internal,
    const float* __restrict__ W, const float* __restrict__ bias)
{
    __shared__ float xs[128 * GS];
    __shared__ float ws[128 * GS];
    const float* X = x_internal ? g_y0 : Xe;

    const int n0 = blockIdx.x * 128;
    const int m0 = blockIdx.y * 128;
    const int tid = threadIdx.x;
    const int tx = tid & 15, ty = tid >> 4;

    unsigned long long acc[8][8];
#pragma unroll
    for (int i = 0; i < 8; i++)
#pragma unroll
        for (int j = 0; j < 8; j++) acc[i][j] = 0ull;

    const float* Xp = X + (size_t)m0 * 512;
    const float* Wp = W + (size_t)n0 * 512;

    int aoff[8], woff[8];
#pragma unroll
    for (int i = 0; i < 8; i++) aoff[i] = (ty + 16 * i) * GS;
#pragma unroll
    for (int j = 0; j < 8; j++) woff[j] = (tx + 16 * j) * GS;

    for (int kb = 0; kb < 512; kb += 32) {
#pragma unroll
        for (int r = 0; r < 4; r++) {
            int idx = tid + r * 256;
            int row = idx >> 3, f4 = (idx & 7) * 4;
            ulonglong2 xv = *reinterpret_cast<const ulonglong2*>(
                &Xp[(size_t)row * 512 + kb + f4]);
            ulonglong2 wv = *reinterpret_cast<const ulonglong2*>(
                &Wp[(size_t)row * 512 + kb + f4]);
            int base = row * GS + f4;
            *reinterpret_cast<unsigned long long*>(&xs[base])     = xv.x;
            *reinterpret_cast<unsigned long long*>(&xs[base + 2]) = xv.y;
            *reinterpret_cast<unsigned long long*>(&ws[base])     = wv.x;
            *reinterpret_cast<unsigned long long*>(&ws[base + 2]) = wv.y;
        }
        __syncthreads();

#pragma unroll 4
        for (int k2 = 0; k2 < 16; k2++) {
            unsigned long long a[8], w[8];
#pragma unroll
            for (int i = 0; i < 8; i++)
                a[i] = *reinterpret_cast<const unsigned long long*>(&xs[aoff[i] + 2 * k2]);
#pragma unroll
            for (int j = 0; j < 8; j++)
                w[j] = *reinterpret_cast<const unsigned long long*>(&ws[woff[j] + 2 * k2]);
#pragma unroll
            for (int i = 0; i < 8; i++)
#pragma unroll
                for (int j = 0; j < 8; j++)
                    ffma2(acc[i][j], a[i], w[j]);
        }
        __syncthreads();
    }

#pragma unroll
    for (int i = 0; i < 8; i++) {
        int m = m0 + ty + 16 * i;
#pragma unroll
        for (int j = 0; j < 8; j++) {
            int n = n0 + tx + 16 * j;
            g_gi[(size_t)m * G3 + n] = acc_sum(acc[i][j]) + bias[n];
        }
    }
}

// ---------------- persistent recurrence kernel ----------------
// 96 CTAs = 24 n-tiles x 4 k-chunks; 256 threads.
#define RS 132   // 128 + 4 pad
__global__ void __launch_bounds__(256, 1) k_rec(
    const float* __restrict__ Whh, const float* __restrict__ bhh,
    const float* __restrict__ lng, const float* __restrict__ lnb,
    float* __restrict__ y_ext, int y_internal, float* __restrict__ hlast)
{
    extern __shared__ float sm[];
    float* wsm = sm;             // [64*RS] Whh tile, cached across all steps
    float* hs  = sm + 64 * RS;   // [64*RS] h tile; reused by phase 2

    const int tid = threadIdx.x;
    const int bx  = blockIdx.x;
    const int nt  = bx % 24;
    const int kc  = bx / 24;
    const int n0  = nt * 64;
    const int k0  = kc * 128;
    float* y = y_internal ? g_y0 : y_ext;

    // stage Whh tile once: wsm[n][kk]
#pragma unroll
    for (int r = 0; r < 8; r++) {
        int idx = tid + r * 256;
        int n = idx >> 5, kf4 = (idx & 31) * 4;
        *reinterpret_cast<float4*>(&wsm[n * RS + kf4]) =
            *reinterpret_cast<const float4*>(&Whh[(size_t)(n0 + n) * 512 + k0 + kf4]);
    }

    const int tx = tid & 15, ty = tid >> 4;
    int aoff[4], woff[4];
#pragma unroll
    for (int i = 0; i < 4; i++) aoff[i] = (ty + 16 * i) * RS;
#pragma unroll
    for (int j = 0; j < 4; j++) woff[j] = (tx + 16 * j) * RS;

    for (int t = 0; t < T_; t++) {
        __syncthreads();
        // stage h tile: hs[b][kk]
#pragma unroll
        for (int r = 0; r < 8; r++) {
            int idx = tid + r * 256;
            int b = idx >> 5, kf4 = (idx & 31) * 4;
            *reinterpret_cast<float4*>(&hs[b * RS + kf4]) =
                *reinterpret_cast<const float4*>(&g_h[b * 512 + k0 + kf4]);
        }
        __syncthreads();

        unsigned long long acc[4][4];
#pragma unroll
        for (int i = 0; i < 4; i++)
#pragma unroll
            for (int j = 0; j < 4; j++) acc[i][j] = 0ull;

#pragma unroll 8
        for (int k4 = 0; k4 < 128; k4 += 4) {
            ulonglong2 av[4], wv[4];
#pragma unroll
            for (int i = 0; i < 4; i++)
                av[i] = *reinterpret_cast<const ulonglong2*>(&hs[aoff[i] + k4]);
#pragma unroll
            for (int j = 0; j < 4; j++)
                wv[j] = *reinterpret_cast<const ulonglong2*>(&wsm[woff[j] + k4]);
#pragma unroll
            for (int i = 0; i < 4; i++)
#pragma unroll
                for (int j = 0; j < 4; j++) {
                    ffma2(acc[i][j], av[i].x, wv[j].x);
                    ffma2(acc[i][j], av[i].y, wv[j].y);
                }
        }

#pragma unroll
        for (int i = 0; i < 4; i++) {
            int b = ty + 16 * i;
#pragma unroll
            for (int j = 0; j < 4; j++)
                g_ghp[(size_t)(kc * 64 + b) * G3 + (n0 + tx + 16 * j)] =
                    acc_sum(acc[i][j]);
        }

        gridbar(2 * (unsigned)t + 1u);

        // ---------- phase 2: CTA b handles batch row b (256 threads) ----------
        if (bx < B_) {
            const int b = bx;
            float* A   = hs;           // pre_r
            float* Bv  = hs + 512;     // pre_i -> inputgate
            float* Cc  = hs + 1024;    // gh_n -> pre_n
            float* Dd  = hs + 1536;    // gi_n
            float* red = hs + 2048;
            const float* git = g_gi + ((size_t)t * B_ + b) * G3;

            for (int j = tid; j < 512; j += 256) {
                float s_r = bhh[j], s_i = bhh[512 + j], s_n = bhh[1024 + j];
#pragma unroll
                for (int kq = 0; kq < 4; kq++) {
                    const float* p = g_ghp + (size_t)(kq * 64 + b) * G3;
                    s_r += p[j]; s_i += p[512 + j]; s_n += p[1024 + j];
                }
                A[j]  = git[j] + s_r;
                Bv[j] = git[512 + j] + s_i;
                Cc[j] = s_n;
                Dd[j] = git[1024 + j];
            }
            __syncthreads();

            float sr = 0.f, qr = 0.f, si = 0.f, qi = 0.f;
            for (int j = tid; j < 512; j += 256) {
                float v = A[j];  sr += v; qr += v * v;
                v = Bv[j];       si += v; qi += v * v;
            }
            blockReduce2(sr, qr, red);
            blockReduce2(si, qi, red);
            const float inv = 1.0f / 512.0f;
            float mur = sr * inv, rr = rsqrtf(qr * inv - mur * mur + 1e-5f);
            float mui = si * inv, ri = rsqrtf(qi * inv - mui * mui + 1e-5f);

            for (int j = tid; j < 512; j += 256) {
                float xr = (A[j] - mur) * rr * lng[j] + lnb[j];
                float rg = 1.0f / (1.0f + __expf(-xr));
                float xi = (Bv[j] - mui) * ri * lng[512 + j] + lnb[512 + j];
                Bv[j] = 1.0f / (1.0f + __expf(-xi));
                Cc[j] = Dd[j] + rg * Cc[j];
            }
            __syncthreads();

            float sn = 0.f, qn = 0.f;
            for (int j = tid; j < 512; j += 256) { float v = Cc[j]; sn += v; qn += v * v; }
            blockReduce2(sn, qn, red);
            float mun = sn * inv, rn = rsqrtf(qn * inv - mun * mun + 1e-5f);

            for (int j = tid; j < 512; j += 256) {
                float xn = (Cc[j] - mun) * rn * lng[1024 + j] + lnb[1024 + j];
                float ng = tanhf(xn);
                float hold = g_h[b * 512 + j];
                float hy = ng + Bv[j] * (hold - ng);
                g_h[b * 512 + j] = hy;
                y[((size_t)t * B_ + b) * H_ + j] = hy;
                if (t == T_ - 1) hlast[b * 512 + j] = hy;
            }
        }

        gridbar(2 * (unsigned)t + 2u);
    }
}

// ---------------- launcher ----------------
extern "C" void kernel_launch(void* const* d_in, const int* in_sizes, int n_in,
                              void* d_out, int out_size) {
    (void)in_sizes; (void)n_in;
    const float* x   = (const float*)d_in[0];
    const float* h0  = (const float*)d_in[1];
    const float* Wih = (const float*)d_in[2];
    const float* bih = (const float*)d_in[3];
    const float* Whh = (const float*)d_in[4];
    const float* bhh = (const float*)d_in[5];
    const float* lng = (const float*)d_in[6];
    const float* lnb = (const float*)d_in[7];
    float* out = (float*)d_out;

    const size_t TBH = (size_t)T_ * B_ * H_;
    const size_t LBH = (size_t)2 * B_ * H_;
    bool has_hl = ((size_t)out_size >= TBH + LBH);

    float* hl_dummy = nullptr;
    cudaGetSymbolAddress((void**)&hl_dummy, g_dummy);
    float* hl0 = has_hl ? out + TBH           : hl_dummy;
    float* hl1 = has_hl ? out + TBH + B_ * H_ : hl_dummy;

    const int smem_rec = 2 * 64 * RS * (int)sizeof(float);  // 67,584 B
    cudaFuncSetAttribute(k_rec, cudaFuncAttributeMaxDynamicSharedMemorySize, smem_rec);

    dim3 gg(G3 / 128, (T_ * B_) / 128);  // (12, 256)

    // layer 0
    k_gemm_in<<<gg, 256>>>(x, 0, Wih, bih);
    k_seth<<<(B_ * H_) / 256, 256>>>(h0);
    k_rec<<<NB_REC, 256, smem_rec>>>(Whh, bhh, lng, lnb, out, 1, hl0);

    // layer 1
    k_gemm_in<<<gg, 256>>>(nullptr, 1, Wih + (size_t)G3 * H_, bih + G3);
    k_seth<<<(B_ * H_) / 256, 256>>>(h0 + B_ * H_);
    k_rec<<<NB_REC, 256, smem_rec>>>(Whh + (size_t)G3 * H_, bhh + G3,
                                     lng + G3, lnb + G3,
                                     out, 0, hl1);
}

// round 10
// speedup vs baseline: 1.2605x; 1.0557x over previous
#include <cuda_runtime.h>
#include <cstddef>

#define T_   512
#define B_   64
#define H_   512
#define G3   1536   // 3*H
#define NCTA 128
#define WS   516    // smem row stride in words (512+4; /4 odd => conflict-free LDS.128)

// ---------------- device scratch ----------------
__device__ float g_gi[(size_t)T_ * B_ * G3];   // layer-0 input projection (precomputed)
__device__ float g_y0[(size_t)T_ * B_ * H_];   // layer-0 output sequence
__device__ float g_h0[B_ * H_];
__device__ float g_h1[B_ * H_];
__device__ float g_gh0[B_ * G3];               // layer-0 hidden projection (per superstep)
__device__ float g_gh1[B_ * G3];               // layer-1 hidden projection
__device__ float g_gi1[B_ * G3];               // layer-1 input projection (per superstep)
__device__ float g_dummy[B_ * H_];
__device__ volatile unsigned g_flags[NCTA * 32];

// packed fp32x2 FMA (bit-exact 2x FFMA)
__device__ __forceinline__ void ffma2(unsigned long long& d,
                                      unsigned long long a,
                                      unsigned long long b) {
    asm("fma.rn.f32x2 %0, %1, %2, %0;" : "+l"(d) : "l"(a), "l"(b));
}

__device__ __forceinline__ float acc_sum(unsigned long long v) {
    float2 f;
    asm("mov.b64 {%0, %1}, %2;" : "=f"(f.x), "=f"(f.y) : "l"(v));
    return f.x + f.y;
}

// ---------------- flag grid barrier over 128 co-resident CTAs ----------------
__device__ __forceinline__ void gridbar(unsigned v) {
    __threadfence();                     // release
    __syncthreads();
    if (threadIdx.x == 0) g_flags[blockIdx.x * 32] = v;
    if (threadIdx.x < 32) {
        bool done = false;
        while (!done) {
            done = true;
#pragma unroll
            for (int q = 0; q < 4; q++)
                done &= (g_flags[(threadIdx.x + 32 * q) * 32] >= v);
            if (!done) __nanosleep(50);
        }
        __threadfence();                 // acquire
    }
    __syncthreads();
}

// ---------------- dual block reduction over 256 threads ----------------
__device__ __forceinline__ void blockReduce2(float& a, float& b, float* red) {
    int tid = threadIdx.x, lane = tid & 31, wid = tid >> 5;
#pragma unroll
    for (int o = 16; o; o >>= 1) {
        a += __shfl_down_sync(0xffffffffu, a, o);
        b += __shfl_down_sync(0xffffffffu, b, o);
    }
    if (lane == 0) { red[wid] = a; red[8 + wid] = b; }
    __syncthreads();
    if (tid < 32) {
        a = (lane < 8) ? red[lane] : 0.0f;
        b = (lane < 8) ? red[8 + lane] : 0.0f;
#pragma unroll
        for (int o = 4; o; o >>= 1) {
            a += __shfl_down_sync(0xffffffffu, a, o);
            b += __shfl_down_sync(0xffffffffu, b, o);
        }
        if (lane == 0) { red[16] = a; red[17] = b; }
    }
    __syncthreads();
    a = red[16]; b = red[17];
    __syncthreads();
}

// ---------------- init h states + barrier flags ----------------
__global__ void k_init(const float* __restrict__ h0) {
    int i = blockIdx.x * blockDim.x + threadIdx.x;   // 128*256 = 32768 = B*H
    g_h0[i] = h0[i];
    g_h1[i] = h0[B_ * H_ + i];
    if (i < NCTA * 32) g_flags[i] = 0u;
}

// ---------------- layer-0 input projection: 128x128 tile, 8x8 micro, f32x2 --
#define GS 34
__global__ void __launch_bounds__(256, 1) k_gemm_in(
    const float* __restrict__ X, const float* __restrict__ W,
    const float* __restrict__ bias)
{
    __shared__ float xs[128 * GS];
    __shared__ float ws[128 * GS];

    const int n0 = blockIdx.x * 128;
    const int m0 = blockIdx.y * 128;
    const int tid = threadIdx.x;
    const int tx = tid & 15, ty = tid >> 4;

    unsigned long long acc[8][8];
#pragma unroll
    for (int i = 0; i < 8; i++)
#pragma unroll
        for (int j = 0; j < 8; j++) acc[i][j] = 0ull;

    const float* Xp = X + (size_t)m0 * 512;
    const float* Wp = W + (size_t)n0 * 512;

    int aoff[8], woff[8];
#pragma unroll
    for (int i = 0; i < 8; i++) aoff[i] = (ty + 16 * i) * GS;
#pragma unroll
    for (int j = 0; j < 8; j++) woff[j] = (tx + 16 * j) * GS;

    for (int kb = 0; kb < 512; kb += 32) {
#pragma unroll
        for (int r = 0; r < 4; r++) {
            int idx = tid + r * 256;
            int row = idx >> 3, f4 = (idx & 7) * 4;
            ulonglong2 xv = *reinterpret_cast<const ulonglong2*>(
                &Xp[(size_t)row * 512 + kb + f4]);
            ulonglong2 wv = *reinterpret_cast<const ulonglong2*>(
                &Wp[(size_t)row * 512 + kb + f4]);
            int base = row * GS + f4;
            *reinterpret_cast<unsigned long long*>(&xs[base])     = xv.x;
            *reinterpret_cast<unsigned long long*>(&xs[base + 2]) = xv.y;
            *reinterpret_cast<unsigned long long*>(&ws[base])     = wv.x;
            *reinterpret_cast<unsigned long long*>(&ws[base + 2]) = wv.y;
        }
        __syncthreads();
#pragma unroll 4
        for (int k2 = 0; k2 < 16; k2++) {
            unsigned long long a[8], w[8];
#pragma unroll
            for (int i = 0; i < 8; i++)
                a[i] = *reinterpret_cast<const unsigned long long*>(&xs[aoff[i] + 2 * k2]);
#pragma unroll
            for (int j = 0; j < 8; j++)
                w[j] = *reinterpret_cast<const unsigned long long*>(&ws[woff[j] + 2 * k2]);
#pragma unroll
            for (int i = 0; i < 8; i++)
#pragma unroll
                for (int j = 0; j < 8; j++)
                    ffma2(acc[i][j], a[i], w[j]);
        }
        __syncthreads();
    }
#pragma unroll
    for (int i = 0; i < 8; i++) {
        int m = m0 + ty + 16 * i;
#pragma unroll
        for (int j = 0; j < 8; j++) {
            int n = n0 + tx + 16 * j;
            g_gi[(size_t)m * G3 + n] = acc_sum(acc[i][j]) + bias[n];
        }
    }
}

// ---------------- fused 2-layer pipelined recurrence ----------------
// 128 CTAs, 256 threads. CTAs 0..95: GEMM role = bx>>5 (0: gh0, 1: gh1, 2: gi1),
// 48-col n-tile, full K=512, weight tile resident in smem for the whole kernel.
// Phase 2: CTA bx handles (layer = bx>>6, b = bx&63).
__global__ void __launch_bounds__(256, 1) k_fused(
    const float* __restrict__ Whh0, const float* __restrict__ Whh1,
    const float* __restrict__ Wih1, const float* __restrict__ bih1,
    const float* __restrict__ bhh,  const float* __restrict__ lng,
    const float* __restrict__ lnb,  float* __restrict__ out,
    float* __restrict__ hl0, float* __restrict__ hl1)
{
    extern __shared__ float sm[];
    float* wsm = sm;             // [48*WS] weight tile (persistent)
    float* hs  = sm + 48 * WS;   // [64*WS] input tile; phase-2 scratch overlay

    const int tid  = threadIdx.x;
    const int bx   = blockIdx.x;
    const int role = bx >> 5;          // 0,1,2 gemm; 3 = phase-2-only CTAs
    const int tile = bx & 31;
    const int n0   = tile * 48;

    // ---- stage weight tile once ----
    if (role < 3) {
        const float* Wp = (role == 0) ? (Whh0 + (size_t)n0 * 512)
                        : (role == 1) ? (Whh1 + (size_t)n0 * 512)
                                      : (Wih1 + (size_t)n0 * 512);
#pragma unroll
        for (int r = 0; r < 24; r++) {
            int idx = tid + r * 256;            // 48*128 f4 units
            int n = idx >> 7, c4 = (idx & 127) * 4;
            *reinterpret_cast<float4*>(&wsm[n * WS + c4]) =
                *reinterpret_cast<const float4*>(&Wp[(size_t)n * 512 + c4]);
        }
    }

    const int tx  = tid & 7;           // n within tile
    const int tyy = tid >> 3;          // 0..31, b = tyy + 32*i
    int aoff[2], woff[6];
#pragma unroll
    for (int i = 0; i < 2; i++) aoff[i] = (tyy + 32 * i) * WS;
#pragma unroll
    for (int j = 0; j < 6; j++) woff[j] = (tx + 8 * j) * WS;

    const int layer = bx >> 6;         // phase-2 unit
    const int b2    = bx & 63;

    for (int s = 0; s <= T_; s++) {
        // ================= phase 1: three GEMMs =================
        bool gemm_on = (role == 0) ? (s < T_) : (role < 3 && s >= 1);
        if (gemm_on) {
            const float* inp = (role == 0) ? g_h0
                             : (role == 1) ? g_h1
                                           : (g_y0 + (size_t)(s - 1) * B_ * H_);
            __syncthreads();   // protect hs vs previous phase-2 scratch use
#pragma unroll
            for (int r = 0; r < 32; r++) {
                int idx = tid + r * 256;        // 64*128 f4 units
                int b = idx >> 7, c4 = (idx & 127) * 4;
                *reinterpret_cast<float4*>(&hs[b * WS + c4]) =
                    *reinterpret_cast<const float4*>(&inp[b * 512 + c4]);
            }
            __syncthreads();

            unsigned long long acc[2][6];
#pragma unroll
            for (int i = 0; i < 2; i++)
#pragma unroll
                for (int j = 0; j < 6; j++) acc[i][j] = 0ull;

#pragma unroll 2
            for (int k4 = 0; k4 < 512; k4 += 4) {
                ulonglong2 av[2], wv[6];
#pragma unroll
                for (int i = 0; i < 2; i++)
                    av[i] = *reinterpret_cast<const ulonglong2*>(&hs[aoff[i] + k4]);
#pragma unroll
                for (int j = 0; j < 6; j++)
                    wv[j] = *reinterpret_cast<const ulonglong2*>(&wsm[woff[j] + k4]);
#pragma unroll
                for (int i = 0; i < 2; i++)
#pragma unroll
                    for (int j = 0; j < 6; j++) {
                        ffma2(acc[i][j], av[i].x, wv[j].x);
                        ffma2(acc[i][j], av[i].y, wv[j].y);
                    }
            }

            float* gout = (role == 0) ? g_gh0 : (role == 1) ? g_gh1 : g_gi1;
#pragma unroll
            for (int i = 0; i < 2; i++) {
                int b = tyy + 32 * i;
#pragma unroll
                for (int j = 0; j < 6; j++)
                    gout[(size_t)b * G3 + n0 + tx + 8 * j] = acc_sum(acc[i][j]);
            }
        }

        gridbar(2 * (unsigned)s + 1u);

        // ================= phase 2: one (layer, b) unit per CTA =================
        bool p2_on = (layer == 0) ? (s < T_) : (s >= 1);
        if (p2_on) {
            const int t = (layer == 0) ? s : (s - 1);
            const float* gh = (layer ? g_gh1 : g_gh0) + (size_t)b2 * G3;
            const float* gi = layer ? (g_gi1 + (size_t)b2 * G3)
                                    : (g_gi + ((size_t)t * B_ + b2) * G3);
            const float* bh = bhh + layer * G3;
            const float* lg = lng + layer * G3;
            const float* lb = lnb + layer * G3;

            float* A   = hs;           // pre_r
            float* Bv  = hs + 512;     // pre_i -> inputgate
            float* Cc  = hs + 1024;    // gh_n -> pre_n
            float* Dd  = hs + 1536;    // gi_n
            float* red = hs + 2048;

            __syncthreads();           // hs reuse ordering within CTA
            for (int j = tid; j < 512; j += 256) {
                float br = layer ? bih1[j]        : 0.0f;
                float bi = layer ? bih1[512 + j]  : 0.0f;
                float bn = layer ? bih1[1024 + j] : 0.0f;
                A[j]  = gi[j]        + br + gh[j]        + bh[j];
                Bv[j] = gi[512 + j]  + bi + gh[512 + j]  + bh[512 + j];
                Cc[j] = gh[1024 + j] + bh[1024 + j];
                Dd[j] = gi[1024 + j] + bn;
            }
            __syncthreads();

            float sr = 0.f, qr = 0.f, si = 0.f, qi = 0.f;
            for (int j = tid; j < 512; j += 256) {
                float v = A[j];  sr += v; qr += v * v;
                v = Bv[j];       si += v; qi += v * v;
            }
            blockReduce2(sr, qr, red);
            blockReduce2(si, qi, red);
            const float inv = 1.0f / 512.0f;
            float mur = sr * inv, rr = rsqrtf(qr * inv - mur * mur + 1e-5f);
            float mui = si * inv, ri = rsqrtf(qi * inv - mui * mui + 1e-5f);

            for (int j = tid; j < 512; j += 256) {
                float xr = (A[j] - mur) * rr * lg[j] + lb[j];
                float rg = 1.0f / (1.0f + __expf(-xr));
                float xi = (Bv[j] - mui) * ri * lg[512 + j] + lb[512 + j];
                Bv[j] = 1.0f / (1.0f + __expf(-xi));
                Cc[j] = Dd[j] + rg * Cc[j];
            }
            __syncthreads();

            float sn = 0.f, qn = 0.f;
            for (int j = tid; j < 512; j += 256) { float v = Cc[j]; sn += v; qn += v * v; }
            blockReduce2(sn, qn, red);
            float mun = sn * inv, rn = rsqrtf(qn * inv - mun * mun + 1e-5f);

            float* hcur = layer ? g_h1 : g_h0;
            for (int j = tid; j < 512; j += 256) {
                float xn = (Cc[j] - mun) * rn * lg[1024 + j] + lb[1024 + j];
                float ng = tanhf(xn);
                float hold = hcur[b2 * 512 + j];
                float hy = ng + Bv[j] * (hold - ng);
                hcur[b2 * 512 + j] = hy;
                if (layer == 0) {
                    g_y0[((size_t)t * B_ + b2) * H_ + j] = hy;
                    if (t == T_ - 1) hl0[b2 * 512 + j] = hy;
                } else {
                    out[((size_t)t * B_ + b2) * H_ + j] = hy;
                    if (t == T_ - 1) hl1[b2 * 512 + j] = hy;
                }
            }
        }

        gridbar(2 * (unsigned)s + 2u);
    }
}

// ---------------- launcher ----------------
extern "C" void kernel_launch(void* const* d_in, const int* in_sizes, int n_in,
                              void* d_out, int out_size) {
    (void)in_sizes; (void)n_in;
    const float* x   = (const float*)d_in[0];
    const float* h0  = (const float*)d_in[1];
    const float* Wih = (const float*)d_in[2];
    const float* bih = (const float*)d_in[3];
    const float* Whh = (const float*)d_in[4];
    const float* bhh = (const float*)d_in[5];
    const float* lng = (const float*)d_in[6];
    const float* lnb = (const float*)d_in[7];
    float* out = (float*)d_out;

    const size_t TBH = (size_t)T_ * B_ * H_;
    const size_t LBH = (size_t)2 * B_ * H_;
    bool has_hl = ((size_t)out_size >= TBH + LBH);

    float* hl_dummy = nullptr;
    cudaGetSymbolAddress((void**)&hl_dummy, g_dummy);
    float* hl0 = has_hl ? out + TBH           : hl_dummy;
    float* hl1 = has_hl ? out + TBH + B_ * H_ : hl_dummy;

    const int smem_fused = (48 + 64) * WS * (int)sizeof(float);  // 231,168 B
    cudaFuncSetAttribute(k_fused, cudaFuncAttributeMaxDynamicSharedMemorySize,
                         smem_fused);

    // layer-0 input projection for all timesteps (parallel GEMM)
    dim3 gg(G3 / 128, (T_ * B_) / 128);  // (12, 256)
    k_gemm_in<<<gg, 256>>>(x, Wih, bih);

    // init states + flags
    k_init<<<NCTA, 256>>>(h0);

    // fused pipelined recurrence for both layers
    k_fused<<<NCTA, 256, smem_fused>>>(
        Whh, Whh + (size_t)G3 * H_,
        Wih + (size_t)G3 * H_, bih + G3,
        bhh, lng, lnb, out, hl0, hl1);
}

// round 11
// speedup vs baseline: 2.2297x; 1.7690x over previous
#include <cuda_runtime.h>
#include <cuda_bf16.h>
#include <cstddef>
#include <cstdint>

#define T_   512
#define B_   64
#define H_   512
#define G3   1536   // 3*H
#define NCTA 128

// ---------------- device scratch ----------------
__device__ float g_gi[(size_t)T_ * B_ * G3];   // layer-0 input projection
__device__ float g_y0[(size_t)T_ * B_ * H_];   // layer-0 output sequence
__device__ float g_h0[B_ * H_];
__device__ float g_h1[B_ * H_];
__device__ float g_gh0[B_ * G3];
__device__ float g_gh1[B_ * G3];
__device__ float g_gi1[B_ * G3];
__device__ float g_dummy[B_ * H_];
__device__ volatile unsigned g_flags[NCTA * 32];

// ---------------- f32x2 FMA (for k_gemm_in) ----------------
__device__ __forceinline__ void ffma2(unsigned long long& d,
                                      unsigned long long a,
                                      unsigned long long b) {
    asm("fma.rn.f32x2 %0, %1, %2, %0;" : "+l"(d) : "l"(a), "l"(b));
}
__device__ __forceinline__ float acc_sum(unsigned long long v) {
    float2 f;
    asm("mov.b64 {%0, %1}, %2;" : "=f"(f.x), "=f"(f.y) : "l"(v));
    return f.x + f.y;
}

// ---------------- mma / ldmatrix wrappers ----------------
__device__ __forceinline__ void mma_bf16(float* d, const uint32_t* a, const uint32_t* b) {
    asm volatile(
        "mma.sync.aligned.m16n8k16.row.col.f32.bf16.bf16.f32 "
        "{%0,%1,%2,%3}, {%4,%5,%6,%7}, {%8,%9}, {%0,%1,%2,%3};"
        : "+f"(d[0]), "+f"(d[1]), "+f"(d[2]), "+f"(d[3])
        : "r"(a[0]), "r"(a[1]), "r"(a[2]), "r"(a[3]), "r"(b[0]), "r"(b[1]));
}
__device__ __forceinline__ void ldsm_x4(uint32_t* r, uint32_t addr) {
    asm volatile("ldmatrix.sync.aligned.m8n8.x4.shared.b16 {%0,%1,%2,%3}, [%4];"
                 : "=r"(r[0]), "=r"(r[1]), "=r"(r[2]), "=r"(r[3]) : "r"(addr));
}
__device__ __forceinline__ void ldsm_x2(uint32_t* r, uint32_t addr) {
    asm volatile("ldmatrix.sync.aligned.m8n8.x2.shared.b16 {%0,%1}, [%2];"
                 : "=r"(r[0]), "=r"(r[1]) : "r"(addr));
}
// pack two f32 -> bf16x2 {lo=x, hi=y}
__device__ __forceinline__ uint32_t pack_bf16(float x, float y) {
    uint32_t p;
    asm("cvt.rn.bf16x2.f32 %0, %1, %2;" : "=r"(p) : "f"(y), "f"(x));
    return p;
}
__device__ __forceinline__ float bf_lo(uint32_t p) { return __uint_as_float(p << 16); }
__device__ __forceinline__ float bf_hi(uint32_t p) { return __uint_as_float(p & 0xffff0000u); }

// smem swizzle: row stride 1024B (512 bf16), XOR 16B-chunk index with row%8
__device__ __forceinline__ uint32_t swz(uint32_t row, uint32_t kbyte) {
    return (((row << 10) + kbyte) ^ ((row & 7u) << 4));
}

// smem plane byte offsets (k_fused)
#define SM_AHI 0
#define SM_ALO 65536
#define SM_BHI 131072
#define SM_BLO 180224
#define SM_FUSED 229376

// ---------------- flag grid barrier over 128 co-resident CTAs ----------------
__device__ __forceinline__ void gridbar(unsigned v) {
    __threadfence();
    __syncthreads();
    if (threadIdx.x == 0) g_flags[blockIdx.x * 32] = v;
    if (threadIdx.x < 32) {
        bool done = false;
        while (!done) {
            done = true;
#pragma unroll
            for (int q = 0; q < 4; q++)
                done &= (g_flags[(threadIdx.x + 32 * q) * 32] >= v);
            if (!done) __nanosleep(50);
        }
        __threadfence();
    }
    __syncthreads();
}

// ---------------- dual block reduction over 256 threads ----------------
__device__ __forceinline__ void blockReduce2(float& a, float& b, float* red) {
    int tid = threadIdx.x, lane = tid & 31, wid = tid >> 5;
#pragma unroll
    for (int o = 16; o; o >>= 1) {
        a += __shfl_down_sync(0xffffffffu, a, o);
        b += __shfl_down_sync(0xffffffffu, b, o);
    }
    if (lane == 0) { red[wid] = a; red[8 + wid] = b; }
    __syncthreads();
    if (tid < 32) {
        a = (lane < 8) ? red[lane] : 0.0f;
        b = (lane < 8) ? red[8 + lane] : 0.0f;
#pragma unroll
        for (int o = 4; o; o >>= 1) {
            a += __shfl_down_sync(0xffffffffu, a, o);
            b += __shfl_down_sync(0xffffffffu, b, o);
        }
        if (lane == 0) { red[16] = a; red[17] = b; }
    }
    __syncthreads();
    a = red[16]; b = red[17];
    __syncthreads();
}

// ---------------- init ----------------
__global__ void k_init(const float* __restrict__ h0) {
    int i = blockIdx.x * blockDim.x + threadIdx.x;
    g_h0[i] = h0[i];
    g_h1[i] = h0[B_ * H_ + i];
    if (i < NCTA * 32) g_flags[i] = 0u;
}

// ---------------- layer-0 input projection (f32x2 SIMT, unchanged) ----------
#define GS 34
__global__ void __launch_bounds__(256, 1) k_gemm_in(
    const float* __restrict__ X, const float* __restrict__ W,
    const float* __restrict__ bias)
{
    __shared__ float xs[128 * GS];
    __shared__ float ws[128 * GS];

    const int n0 = blockIdx.x * 128;
    const int m0 = blockIdx.y * 128;
    const int tid = threadIdx.x;
    const int tx = tid & 15, ty = tid >> 4;

    unsigned long long acc[8][8];
#pragma unroll
    for (int i = 0; i < 8; i++)
#pragma unroll
        for (int j = 0; j < 8; j++) acc[i][j] = 0ull;

    const float* Xp = X + (size_t)m0 * 512;
    const float* Wp = W + (size_t)n0 * 512;

    int aoff[8], woff[8];
#pragma unroll
    for (int i = 0; i < 8; i++) aoff[i] = (ty + 16 * i) * GS;
#pragma unroll
    for (int j = 0; j < 8; j++) woff[j] = (tx + 16 * j) * GS;

    for (int kb = 0; kb < 512; kb += 32) {
#pragma unroll
        for (int r = 0; r < 4; r++) {
            int idx = tid + r * 256;
            int row = idx >> 3, f4 = (idx & 7) * 4;
            ulonglong2 xv = *reinterpret_cast<const ulonglong2*>(
                &Xp[(size_t)row * 512 + kb + f4]);
            ulonglong2 wv = *reinterpret_cast<const ulonglong2*>(
                &Wp[(size_t)row * 512 + kb + f4]);
            int base = row * GS + f4;
            *reinterpret_cast<unsigned long long*>(&xs[base])     = xv.x;
            *reinterpret_cast<unsigned long long*>(&xs[base + 2]) = xv.y;
            *reinterpret_cast<unsigned long long*>(&ws[base])     = wv.x;
            *reinterpret_cast<unsigned long long*>(&ws[base + 2]) = wv.y;
        }
        __syncthreads();
#pragma unroll 4
        for (int k2 = 0; k2 < 16; k2++) {
            unsigned long long a[8], w[8];
#pragma unroll
            for (int i = 0; i < 8; i++)
                a[i] = *reinterpret_cast<const unsigned long long*>(&xs[aoff[i] + 2 * k2]);
#pragma unroll
            for (int j = 0; j < 8; j++)
                w[j] = *reinterpret_cast<const unsigned long long*>(&ws[woff[j] + 2 * k2]);
#pragma unroll
            for (int i = 0; i < 8; i++)
#pragma unroll
                for (int j = 0; j < 8; j++)
                    ffma2(acc[i][j], a[i], w[j]);
        }
        __syncthreads();
    }
#pragma unroll
    for (int i = 0; i < 8; i++) {
        int m = m0 + ty + 16 * i;
#pragma unroll
        for (int j = 0; j < 8; j++) {
            int n = n0 + tx + 16 * j;
            g_gi[(size_t)m * G3 + n] = acc_sum(acc[i][j]) + bias[n];
        }
    }
}

// ---------------- fused 2-layer pipelined recurrence (bf16 3-mma GEMM) ------
// 128 CTAs, 256 threads. GEMM CTAs 0..95: role = bx>>5 (gh0/gh1/gi1), 48-col
// n-tile, full K=512, weights as resident bf16 hi/lo planes. Phase 2: CTA bx
// handles (layer = bx>>6, b = bx&63).
__global__ void __launch_bounds__(256, 1) k_fused(
    const float* __restrict__ Whh0, const float* __restrict__ Whh1,
    const float* __restrict__ Wih1, const float* __restrict__ bih1,
    const float* __restrict__ bhh,  const float* __restrict__ lng,
    const float* __restrict__ lnb,  float* __restrict__ out,
    float* __restrict__ hl0, float* __restrict__ hl1)
{
    extern __shared__ char smem_raw[];
    float* scratch = reinterpret_cast<float*>(smem_raw);   // phase-2 overlay (A_hi region)

    uint32_t sbase;
    asm("{.reg .u64 t; cvta.to.shared.u64 t, %1; cvt.u32.u64 %0, t;}"
        : "=r"(sbase) : "l"(smem_raw));

    const int tid  = threadIdx.x;
    const int bx   = blockIdx.x;
    const int role = bx >> 5;          // 0,1,2 gemm; 3 = phase-2-only
    const int tile = bx & 31;
    const int n0   = tile * 48;

    // ---- stage + convert weight tile once: 48 x 512 fp32 -> bf16 hi/lo ----
    if (role < 3) {
        const float* Wp = (role == 0) ? (Whh0 + (size_t)n0 * 512)
                        : (role == 1) ? (Whh1 + (size_t)n0 * 512)
                                      : (Wih1 + (size_t)n0 * 512);
#pragma unroll
        for (int r = 0; r < 24; r++) {
            int idx = tid + r * 256;             // 48*128 float4 units
            int row = idx >> 7, k = (idx & 127) * 4;
            float4 v = *reinterpret_cast<const float4*>(&Wp[(size_t)row * 512 + k]);
            uint32_t p0 = pack_bf16(v.x, v.y), p1 = pack_bf16(v.z, v.w);
            uint32_t q0 = pack_bf16(v.x - bf_lo(p0), v.y - bf_hi(p0));
            uint32_t q1 = pack_bf16(v.z - bf_lo(p1), v.w - bf_hi(p1));
            uint32_t off = swz((uint32_t)row, (uint32_t)k * 2);
            *reinterpret_cast<uint2*>(smem_raw + SM_BHI + off) = make_uint2(p0, p1);
            *reinterpret_cast<uint2*>(smem_raw + SM_BLO + off) = make_uint2(q0, q1);
        }
    }

    // ---- per-warp fragment address precompute ----
    const int lane = tid & 31;
    const int warp = tid >> 5;
    const int mb   = (warp & 3) * 16;        // m16 tile base (b rows)
    const int nw   = (warp >> 2) * 24;       // n24 warp base (tile-local)

    const uint32_t aRow  = (uint32_t)(mb + (lane & 15));
    const uint32_t aPre  = (aRow << 10) + (uint32_t)((lane >> 4) * 16);
    const uint32_t aXor  = (aRow & 7u) << 4;
    const uint32_t b4Row = (uint32_t)(nw + ((lane >> 4) << 3) + (lane & 7));
    const uint32_t b4Pre = (b4Row << 10) + (uint32_t)(((lane >> 3) & 1) * 16);
    const uint32_t b4Xor = (b4Row & 7u) << 4;
    const int l2 = lane & 15;
    const uint32_t b2Row = (uint32_t)(nw + 16 + (l2 & 7));
    const uint32_t b2Pre = (b2Row << 10) + (uint32_t)((l2 >> 3) * 16);
    const uint32_t b2Xor = (b2Row & 7u) << 4;

    const int layer = bx >> 6;
    const int b2i   = bx & 63;

    for (int s = 0; s <= T_; s++) {
        // ================= phase 1: three GEMMs on tensor cores =================
        bool gemm_on = (role == 0) ? (s < T_) : (role < 3 && s >= 1);
        if (gemm_on) {
            const float* inp = (role == 0) ? g_h0
                             : (role == 1) ? g_h1
                                           : (g_y0 + (size_t)(s - 1) * B_ * H_);
            __syncthreads();   // protect smem vs previous phase-2 scratch
            // stage + convert h tile: 64 x 512 fp32 -> bf16 hi/lo planes
#pragma unroll
            for (int r = 0; r < 32; r++) {
                int idx = tid + r * 256;          // 64*128 float4 units
                int row = idx >> 7, k = (idx & 127) * 4;
                float4 v = *reinterpret_cast<const float4*>(&inp[row * 512 + k]);
                uint32_t p0 = pack_bf16(v.x, v.y), p1 = pack_bf16(v.z, v.w);
                uint32_t q0 = pack_bf16(v.x - bf_lo(p0), v.y - bf_hi(p0));
                uint32_t q1 = pack_bf16(v.z - bf_lo(p1), v.w - bf_hi(p1));
                uint32_t off = swz((uint32_t)row, (uint32_t)k * 2);
                *reinterpret_cast<uint2*>(smem_raw + SM_AHI + off) = make_uint2(p0, p1);
                *reinterpret_cast<uint2*>(smem_raw + SM_ALO + off) = make_uint2(q0, q1);
            }
            __syncthreads();

            float accH[3][4], accX[3][4];
#pragma unroll
            for (int n = 0; n < 3; n++)
#pragma unroll
                for (int i = 0; i < 4; i++) { accH[n][i] = 0.f; accX[n][i] = 0.f; }

#pragma unroll 4
            for (uint32_t kb = 0; kb < 1024; kb += 32) {   // k16 steps (bytes)
                uint32_t ah[4], al[4], bh01[4], bl01[4], bh2[2], bl2[2];
                uint32_t aoff  = ((aPre + kb) ^ aXor);
                uint32_t b4off = ((b4Pre + kb) ^ b4Xor);
                uint32_t b2off = ((b2Pre + kb) ^ b2Xor);
                ldsm_x4(ah,   sbase + SM_AHI + aoff);
                ldsm_x4(al,   sbase + SM_ALO + aoff);
                ldsm_x4(bh01, sbase + SM_BHI + b4off);
                ldsm_x4(bl01, sbase + SM_BLO + b4off);
                ldsm_x2(bh2,  sbase + SM_BHI + b2off);
                ldsm_x2(bl2,  sbase + SM_BLO + b2off);

                mma_bf16(accH[0], ah, bh01 + 0);
                mma_bf16(accH[1], ah, bh01 + 2);
                mma_bf16(accH[2], ah, bh2);
                mma_bf16(accX[0], ah, bl01 + 0);
                mma_bf16(accX[1], ah, bl01 + 2);
                mma_bf16(accX[2], ah, bl2);
                mma_bf16(accX[0], al, bh01 + 0);
                mma_bf16(accX[1], al, bh01 + 2);
                mma_bf16(accX[2], al, bh2);
            }

            float* gout = (role == 0) ? g_gh0 : (role == 1) ? g_gh1 : g_gi1;
            const int r0 = mb + (lane >> 2);
            const int c0 = n0 + nw + 2 * (lane & 3);
#pragma unroll
            for (int n = 0; n < 3; n++) {
                int c = c0 + 8 * n;
                float2 v0 = make_float2(accH[n][0] + accX[n][0],
                                        accH[n][1] + accX[n][1]);
                float2 v1 = make_float2(accH[n][2] + accX[n][2],
                                        accH[n][3] + accX[n][3]);
                *reinterpret_cast<float2*>(&gout[(size_t)r0 * G3 + c])       = v0;
                *reinterpret_cast<float2*>(&gout[(size_t)(r0 + 8) * G3 + c]) = v1;
            }
        }

        gridbar(2 * (unsigned)s + 1u);

        // ================= phase 2: one (layer, b) unit per CTA =================
        bool p2_on = (layer == 0) ? (s < T_) : (s >= 1);
        if (p2_on) {
            const int t = (layer == 0) ? s : (s - 1);
            const float* gh = (layer ? g_gh1 : g_gh0) + (size_t)b2i * G3;
            const float* gi = layer ? (g_gi1 + (size_t)b2i * G3)
                                    : (g_gi + ((size_t)t * B_ + b2i) * G3);
            const float* bh = bhh + layer * G3;
            const float* lg = lng + layer * G3;
            const float* lb = lnb + layer * G3;

            float* A   = scratch;
            float* Bv  = scratch + 512;
            float* Cc  = scratch + 1024;
            float* Dd  = scratch + 1536;
            float* red = scratch + 2048;

            __syncthreads();
            for (int j = tid; j < 512; j += 256) {
                float br = layer ? bih1[j]        : 0.0f;
                float bi = layer ? bih1[512 + j]  : 0.0f;
                float bn = layer ? bih1[1024 + j] : 0.0f;
                A[j]  = gi[j]        + br + gh[j]        + bh[j];
                Bv[j] = gi[512 + j]  + bi + gh[512 + j]  + bh[512 + j];
                Cc[j] = gh[1024 + j] + bh[1024 + j];
                Dd[j] = gi[1024 + j] + bn;
            }
            __syncthreads();

            float sr = 0.f, qr = 0.f, si = 0.f, qi = 0.f;
            for (int j = tid; j < 512; j += 256) {
                float v = A[j];  sr += v; qr += v * v;
                v = Bv[j];       si += v; qi += v * v;
            }
            blockReduce2(sr, qr, red);
            blockReduce2(si, qi, red);
            const float inv = 1.0f / 512.0f;
            float mur = sr * inv, rr = rsqrtf(qr * inv - mur * mur + 1e-5f);
            float mui = si * inv, ri = rsqrtf(qi * inv - mui * mui + 1e-5f);

            for (int j = tid; j < 512; j += 256) {
                float xr = (A[j] - mur) * rr * lg[j] + lb[j];
                float rg = 1.0f / (1.0f + __expf(-xr));
                float xi = (Bv[j] - mui) * ri * lg[512 + j] + lb[512 + j];
                Bv[j] = 1.0f / (1.0f + __expf(-xi));
                Cc[j] = Dd[j] + rg * Cc[j];
            }
            __syncthreads();

            float sn = 0.f, qn = 0.f;
            for (int j = tid; j < 512; j += 256) { float v = Cc[j]; sn += v; qn += v * v; }
            blockReduce2(sn, qn, red);
            float mun = sn * inv, rn = rsqrtf(qn * inv - mun * mun + 1e-5f);

            float* hcur = layer ? g_h1 : g_h0;
            for (int j = tid; j < 512; j += 256) {
                float xn = (Cc[j] - mun) * rn * lg[1024 + j] + lb[1024 + j];
                float ng = tanhf(xn);
                float hold = hcur[b2i * 512 + j];
                float hy = ng + Bv[j] * (hold - ng);
                hcur[b2i * 512 + j] = hy;
                if (layer == 0) {
                    g_y0[((size_t)t * B_ + b2i) * H_ + j] = hy;
                    if (t == T_ - 1) hl0[b2i * 512 + j] = hy;
                } else {
                    out[((size_t)t * B_ + b2i) * H_ + j] = hy;
                    if (t == T_ - 1) hl1[b2i * 512 + j] = hy;
                }
            }
        }

        gridbar(2 * (unsigned)s + 2u);
    }
}

// ---------------- launcher ----------------
extern "C" void kernel_launch(void* const* d_in, const int* in_sizes, int n_in,
                              void* d_out, int out_size) {
    (void)in_sizes; (void)n_in;
    const float* x   = (const float*)d_in[0];
    const float* h0  = (const float*)d_in[1];
    const float* Wih = (const float*)d_in[2];
    const float* bih = (const float*)d_in[3];
    const float* Whh = (const float*)d_in[4];
    const float* bhh = (const float*)d_in[5];
    const float* lng = (const float*)d_in[6];
    const float* lnb = (const float*)d_in[7];
    float* out = (float*)d_out;

    const size_t TBH = (size_t)T_ * B_ * H_;
    const size_t LBH = (size_t)2 * B_ * H_;
    bool has_hl = ((size_t)out_size >= TBH + LBH);

    float* hl_dummy = nullptr;
    cudaGetSymbolAddress((void**)&hl_dummy, g_dummy);
    float* hl0 = has_hl ? out + TBH           : hl_dummy;
    float* hl1 = has_hl ? out + TBH + B_ * H_ : hl_dummy;

    cudaFuncSetAttribute(k_fused, cudaFuncAttributeMaxDynamicSharedMemorySize,
                         SM_FUSED);

    dim3 gg(G3 / 128, (T_ * B_) / 128);  // (12, 256)
    k_gemm_in<<<gg, 256>>>(x, Wih, bih);
    k_init<<<NCTA, 256>>>(h0);
    k_fused<<<NCTA, 256, SM_FUSED>>>(
        Whh, Whh + (size_t)G3 * H_,
        Wih + (size_t)G3 * H_, bih + G3,
        bhh, lng, lnb, out, hl0, hl1);
}

// round 12
// speedup vs baseline: 2.9460x; 1.3212x over previous
#include <cuda_runtime.h>
#include <cuda_bf16.h>
#include <cstddef>
#include <cstdint>

#define T_   512
#define B_   64
#define H_   512
#define G3   1536   // 3*H
#define NCTA 128

// ---------------- device scratch ----------------
__device__ float g_y0[(size_t)T_ * B_ * H_];   // layer-0 output sequence
__device__ float g_h0[B_ * H_];
__device__ float g_h1[B_ * H_];
__device__ float g_gh0[B_ * G3];
__device__ float g_gh1[B_ * G3];
__device__ float g_gi0[B_ * G3];
__device__ float g_gi1[B_ * G3];
__device__ float g_dummy[B_ * H_];
__device__ volatile unsigned g_flags[NCTA * 32];

// ---------------- mma / ldmatrix wrappers ----------------
__device__ __forceinline__ void mma_bf16(float* d, const uint32_t* a, const uint32_t* b) {
    asm volatile(
        "mma.sync.aligned.m16n8k16.row.col.f32.bf16.bf16.f32 "
        "{%0,%1,%2,%3}, {%4,%5,%6,%7}, {%8,%9}, {%0,%1,%2,%3};"
        : "+f"(d[0]), "+f"(d[1]), "+f"(d[2]), "+f"(d[3])
        : "r"(a[0]), "r"(a[1]), "r"(a[2]), "r"(a[3]), "r"(b[0]), "r"(b[1]));
}
__device__ __forceinline__ void ldsm_x4(uint32_t* r, uint32_t addr) {
    asm volatile("ldmatrix.sync.aligned.m8n8.x4.shared.b16 {%0,%1,%2,%3}, [%4];"
                 : "=r"(r[0]), "=r"(r[1]), "=r"(r[2]), "=r"(r[3]) : "r"(addr));
}
__device__ __forceinline__ void ldsm_x2(uint32_t* r, uint32_t addr) {
    asm volatile("ldmatrix.sync.aligned.m8n8.x2.shared.b16 {%0,%1}, [%2];"
                 : "=r"(r[0]), "=r"(r[1]) : "r"(addr));
}
// pack two f32 -> bf16x2 {lo=x, hi=y}
__device__ __forceinline__ uint32_t pack_bf16(float x, float y) {
    uint32_t p;
    asm("cvt.rn.bf16x2.f32 %0, %1, %2;" : "=r"(p) : "f"(y), "f"(x));
    return p;
}
__device__ __forceinline__ float bf_lo(uint32_t p) { return __uint_as_float(p << 16); }
__device__ __forceinline__ float bf_hi(uint32_t p) { return __uint_as_float(p & 0xffff0000u); }

// smem swizzle: row stride 1024B (512 bf16), XOR 16B-chunk index with row%8
__device__ __forceinline__ uint32_t swz(uint32_t row, uint32_t kbyte) {
    return (((row << 10) + kbyte) ^ ((row & 7u) << 4));
}

// smem plane byte offsets
#define SM_AHI 0
#define SM_ALO 65536
#define SM_BHI 131072
#define SM_BLO 180224
#define SM_FUSED 229376

// ---------------- flag grid barrier over 128 co-resident CTAs ----------------
__device__ __forceinline__ void gridbar(unsigned v) {
    __threadfence();
    __syncthreads();
    if (threadIdx.x == 0) g_flags[blockIdx.x * 32] = v;
    if (threadIdx.x < 32) {
        bool done = false;
        while (!done) {
            done = true;
#pragma unroll
            for (int q = 0; q < 4; q++)
                done &= (g_flags[(threadIdx.x + 32 * q) * 32] >= v);
            if (!done) __nanosleep(50);
        }
        __threadfence();
    }
    __syncthreads();
}

// ---------------- fused block reductions (256 threads) ----------------
__device__ __forceinline__ void blockReduce4(float& a, float& b, float& c, float& d,
                                             float* red) {
    int tid = threadIdx.x, lane = tid & 31, wid = tid >> 5;
#pragma unroll
    for (int o = 16; o; o >>= 1) {
        a += __shfl_xor_sync(0xffffffffu, a, o);
        b += __shfl_xor_sync(0xffffffffu, b, o);
        c += __shfl_xor_sync(0xffffffffu, c, o);
        d += __shfl_xor_sync(0xffffffffu, d, o);
    }
    if (lane == 0) { red[wid] = a; red[8 + wid] = b; red[16 + wid] = c; red[24 + wid] = d; }
    __syncthreads();
    if (tid < 32) {
        int g = lane >> 3, k = lane & 7;
        float v = red[g * 8 + k];
#pragma unroll
        for (int o = 4; o; o >>= 1) v += __shfl_xor_sync(0xffffffffu, v, o);
        if (k == 0) red[32 + g] = v;
    }
    __syncthreads();
    a = red[32]; b = red[33]; c = red[34]; d = red[35];
}

__device__ __forceinline__ void blockReduce2s(float& a, float& b, float* red) {
    int tid = threadIdx.x, lane = tid & 31, wid = tid >> 5;
#pragma unroll
    for (int o = 16; o; o >>= 1) {
        a += __shfl_xor_sync(0xffffffffu, a, o);
        b += __shfl_xor_sync(0xffffffffu, b, o);
    }
    __syncthreads();   // protect red reuse after blockReduce4 broadcast reads
    if (lane == 0) { red[wid] = a; red[8 + wid] = b; }
    __syncthreads();
    if (tid < 32) {
        int g = lane >> 3, k = lane & 7;
        float v = (g < 2) ? red[g * 8 + k] : 0.0f;
#pragma unroll
        for (int o = 4; o; o >>= 1) v += __shfl_xor_sync(0xffffffffu, v, o);
        if (k == 0 && g < 2) red[40 + g] = v;
    }
    __syncthreads();
    a = red[40]; b = red[41];
}

// ---------------- init ----------------
__global__ void k_init(const float* __restrict__ h0) {
    int i = blockIdx.x * blockDim.x + threadIdx.x;
    g_h0[i] = h0[i];
    g_h1[i] = h0[B_ * H_ + i];
    if (i < NCTA * 32) g_flags[i] = 0u;
}

// ---------------- fused 2-layer pipelined recurrence + in-loop projections ---
// 128 CTAs, 256 threads, 4 GEMM roles (gh0 / gh1 / gi1 / gi0), 32 tiles x 48n,
// full K=512, bf16 3-mma compensated. Phase 2: CTA bx -> (layer=bx>>6, b=bx&63).
__global__ void __launch_bounds__(256, 1) k_fused(
    const float* __restrict__ Whh0, const float* __restrict__ Whh1,
    const float* __restrict__ Wih0, const float* __restrict__ Wih1,
    const float* __restrict__ xin,  const float* __restrict__ bih,
    const float* __restrict__ bhh,  const float* __restrict__ lng,
    const float* __restrict__ lnb,  float* __restrict__ out,
    float* __restrict__ hl0, float* __restrict__ hl1)
{
    extern __shared__ char smem_raw[];
    float* red = reinterpret_cast<float*>(smem_raw);   // phase-2 reduction scratch

    uint32_t sbase;
    asm("{.reg .u64 t; cvta.to.shared.u64 t, %1; cvt.u32.u64 %0, t;}"
        : "=r"(sbase) : "l"(smem_raw));

    const int tid  = threadIdx.x;
    const int bx   = blockIdx.x;
    const int role = bx >> 5;          // 0: gh0, 1: gh1, 2: gi1, 3: gi0
    const int tile = bx & 31;
    const int n0   = tile * 48;

    // ---- stage + convert weight tile once: 48 x 512 fp32 -> bf16 hi/lo ----
    {
        const float* Wp = (role == 0) ? Whh0 : (role == 1) ? Whh1
                        : (role == 2) ? Wih1 : Wih0;
        Wp += (size_t)n0 * 512;
#pragma unroll
        for (int r = 0; r < 24; r++) {
            int idx = tid + r * 256;             // 48*128 float4 units
            int row = idx >> 7, k = (idx & 127) * 4;
            float4 v = *reinterpret_cast<const float4*>(&Wp[(size_t)row * 512 + k]);
            uint32_t p0 = pack_bf16(v.x, v.y), p1 = pack_bf16(v.z, v.w);
            uint32_t q0 = pack_bf16(v.x - bf_lo(p0), v.y - bf_hi(p0));
            uint32_t q1 = pack_bf16(v.z - bf_lo(p1), v.w - bf_hi(p1));
            uint32_t off = swz((uint32_t)row, (uint32_t)k * 2);
            *reinterpret_cast<uint2*>(smem_raw + SM_BHI + off) = make_uint2(p0, p1);
            *reinterpret_cast<uint2*>(smem_raw + SM_BLO + off) = make_uint2(q0, q1);
        }
    }

    // ---- per-warp fragment address precompute ----
    const int lane = tid & 31;
    const int warp = tid >> 5;
    const int mb   = (warp & 3) * 16;        // m16 tile base (b rows)
    const int nw   = (warp >> 2) * 24;       // n24 warp base (tile-local)

    const uint32_t aRow  = (uint32_t)(mb + (lane & 15));
    const uint32_t aPre  = (aRow << 10) + (uint32_t)((lane >> 4) * 16);
    const uint32_t aXor  = (aRow & 7u) << 4;
    const uint32_t b4Row = (uint32_t)(nw + ((lane >> 4) << 3) + (lane & 7));
    const uint32_t b4Pre = (b4Row << 10) + (uint32_t)(((lane >> 3) & 1) * 16);
    const uint32_t b4Xor = (b4Row & 7u) << 4;
    const int l2 = lane & 15;
    const uint32_t b2Row = (uint32_t)(nw + 16 + (l2 & 7));
    const uint32_t b2Pre = (b2Row << 10) + (uint32_t)((l2 >> 3) * 16);
    const uint32_t b2Xor = (b2Row & 7u) << 4;

    const int layer = bx >> 6;
    const int b2i   = bx & 63;

    for (int s = 0; s <= T_; s++) {
        // ================= phase 1: four GEMMs on tensor cores =================
        bool gemm_on = (role == 0 || role == 3) ? (s < T_) : (s >= 1);
        if (gemm_on) {
            const float* inp = (role == 0) ? g_h0
                             : (role == 1) ? g_h1
                             : (role == 2) ? (g_y0 + (size_t)(s - 1) * B_ * H_)
                                           : (xin + (size_t)s * B_ * H_);
            __syncthreads();   // protect smem vs previous phase-2 scratch
            // stage + convert input tile: 64 x 512 fp32 -> bf16 hi/lo planes
#pragma unroll
            for (int r = 0; r < 32; r++) {
                int idx = tid + r * 256;
                int row = idx >> 7, k = (idx & 127) * 4;
                float4 v = *reinterpret_cast<const float4*>(&inp[row * 512 + k]);
                uint32_t p0 = pack_bf16(v.x, v.y), p1 = pack_bf16(v.z, v.w);
                uint32_t q0 = pack_bf16(v.x - bf_lo(p0), v.y - bf_hi(p0));
                uint32_t q1 = pack_bf16(v.z - bf_lo(p1), v.w - bf_hi(p1));
                uint32_t off = swz((uint32_t)row, (uint32_t)k * 2);
                *reinterpret_cast<uint2*>(smem_raw + SM_AHI + off) = make_uint2(p0, p1);
                *reinterpret_cast<uint2*>(smem_raw + SM_ALO + off) = make_uint2(q0, q1);
            }
            __syncthreads();

            float accH[3][4], accX[3][4];
#pragma unroll
            for (int n = 0; n < 3; n++)
#pragma unroll
                for (int i = 0; i < 4; i++) { accH[n][i] = 0.f; accX[n][i] = 0.f; }

#pragma unroll 4
            for (uint32_t kb = 0; kb < 1024; kb += 32) {
                uint32_t ah[4], al[4], bh01[4], bl01[4], bh2[2], bl2[2];
                uint32_t aoff  = ((aPre + kb) ^ aXor);
                uint32_t b4off = ((b4Pre + kb) ^ b4Xor);
                uint32_t b2off = ((b2Pre + kb) ^ b2Xor);
                ldsm_x4(ah,   sbase + SM_AHI + aoff);
                ldsm_x4(al,   sbase + SM_ALO + aoff);
                ldsm_x4(bh01, sbase + SM_BHI + b4off);
                ldsm_x4(bl01, sbase + SM_BLO + b4off);
                ldsm_x2(bh2,  sbase + SM_BHI + b2off);
                ldsm_x2(bl2,  sbase + SM_BLO + b2off);

                mma_bf16(accH[0], ah, bh01 + 0);
                mma_bf16(accH[1], ah, bh01 + 2);
                mma_bf16(accH[2], ah, bh2);
                mma_bf16(accX[0], ah, bl01 + 0);
                mma_bf16(accX[1], ah, bl01 + 2);
                mma_bf16(accX[2], ah, bl2);
                mma_bf16(accX[0], al, bh01 + 0);
                mma_bf16(accX[1], al, bh01 + 2);
                mma_bf16(accX[2], al, bh2);
            }

            float* gout = (role == 0) ? g_gh0 : (role == 1) ? g_gh1
                        : (role == 2) ? g_gi1 : g_gi0;
            const int r0 = mb + (lane >> 2);
            const int c0 = n0 + nw + 2 * (lane & 3);
#pragma unroll
            for (int n = 0; n < 3; n++) {
                int c = c0 + 8 * n;
                float2 v0 = make_float2(accH[n][0] + accX[n][0],
                                        accH[n][1] + accX[n][1]);
                float2 v1 = make_float2(accH[n][2] + accX[n][2],
                                        accH[n][3] + accX[n][3]);
                *reinterpret_cast<float2*>(&gout[(size_t)r0 * G3 + c])       = v0;
                *reinterpret_cast<float2*>(&gout[(size_t)(r0 + 8) * G3 + c]) = v1;
            }

            // role 3: warm L2 with next step's x tile (off critical path)
            if (role == 3 && s + 1 < T_) {
                const float* xn = xin + (size_t)(s + 1) * B_ * H_;
#pragma unroll
                for (int q = 0; q < 4; q++) {
                    const float* p = xn + (size_t)(tid + q * 256) * 32;
                    asm volatile("prefetch.global.L2 [%0];" :: "l"(p));
                }
            }
        }

        gridbar(2 * (unsigned)s + 1u);

        // ================= phase 2: one (layer, b) unit per CTA =================
        bool p2_on = (layer == 0) ? (s < T_) : (s >= 1);
        if (p2_on) {
            const int t = (layer == 0) ? s : (s - 1);
            const float* gh = (layer ? g_gh1 : g_gh0) + (size_t)b2i * G3;
            const float* gi = (layer ? g_gi1 : g_gi0) + (size_t)b2i * G3;
            const float* bi = bih + layer * G3;
            const float* bh = bhh + layer * G3;
            const float* lg = lng + layer * G3;
            const float* lb = lnb + layer * G3;

            const int j0 = 2 * tid;   // two consecutive columns per thread
            __syncthreads();          // red scratch reuse ordering

            float2 ghr = *reinterpret_cast<const float2*>(&gh[j0]);
            float2 ghi = *reinterpret_cast<const float2*>(&gh[512 + j0]);
            float2 ghn = *reinterpret_cast<const float2*>(&gh[1024 + j0]);
            float2 gir = *reinterpret_cast<const float2*>(&gi[j0]);
            float2 gii = *reinterpret_cast<const float2*>(&gi[512 + j0]);
            float2 gin = *reinterpret_cast<const float2*>(&gi[1024 + j0]);
            float2 bir = *reinterpret_cast<const float2*>(&bi[j0]);
            float2 bii = *reinterpret_cast<const float2*>(&bi[512 + j0]);
            float2 bin = *reinterpret_cast<const float2*>(&bi[1024 + j0]);
            float2 bhr = *reinterpret_cast<const float2*>(&bh[j0]);
            float2 bhi = *reinterpret_cast<const float2*>(&bh[512 + j0]);
            float2 bhn = *reinterpret_cast<const float2*>(&bh[1024 + j0]);

            float2 A  = make_float2(gir.x + bir.x + ghr.x + bhr.x,
                                    gir.y + bir.y + ghr.y + bhr.y);
            float2 Bv = make_float2(gii.x + bii.x + ghi.x + bhi.x,
                                    gii.y + bii.y + ghi.y + bhi.y);
            float2 Ch = make_float2(ghn.x + bhn.x, ghn.y + bhn.y);
            float2 Dn = make_float2(gin.x + bin.x, gin.y + bin.y);

            float sr = A.x + A.y,   qr = A.x * A.x + A.y * A.y;
            float si = Bv.x + Bv.y, qi = Bv.x * Bv.x + Bv.y * Bv.y;
            blockReduce4(sr, qr, si, qi, red);

            const float inv = 1.0f / 512.0f;
            float mur = sr * inv, rr = rsqrtf(qr * inv - mur * mur + 1e-5f);
            float mui = si * inv, ri = rsqrtf(qi * inv - mui * mui + 1e-5f);

            float2 lgr = *reinterpret_cast<const float2*>(&lg[j0]);
            float2 lbr = *reinterpret_cast<const float2*>(&lb[j0]);
            float2 lgi = *reinterpret_cast<const float2*>(&lg[512 + j0]);
            float2 lbi = *reinterpret_cast<const float2*>(&lb[512 + j0]);

            float rgx = 1.0f / (1.0f + __expf(-((A.x - mur) * rr * lgr.x + lbr.x)));
            float rgy = 1.0f / (1.0f + __expf(-((A.y - mur) * rr * lgr.y + lbr.y)));
            float igx = 1.0f / (1.0f + __expf(-((Bv.x - mui) * ri * lgi.x + lbi.x)));
            float igy = 1.0f / (1.0f + __expf(-((Bv.y - mui) * ri * lgi.y + lbi.y)));

            float2 Cn = make_float2(Dn.x + rgx * Ch.x, Dn.y + rgy * Ch.y);

            float sn = Cn.x + Cn.y, qn = Cn.x * Cn.x + Cn.y * Cn.y;
            blockReduce2s(sn, qn, red);
            float mun = sn * inv, rn = rsqrtf(qn * inv - mun * mun + 1e-5f);

            float2 lgn = *reinterpret_cast<const float2*>(&lg[1024 + j0]);
            float2 lbn = *reinterpret_cast<const float2*>(&lb[1024 + j0]);

            float ngx = tanhf((Cn.x - mun) * rn * lgn.x + lbn.x);
            float ngy = tanhf((Cn.y - mun) * rn * lgn.y + lbn.y);

            float* hcur = layer ? g_h1 : g_h0;
            float2 hold = *reinterpret_cast<const float2*>(&hcur[b2i * 512 + j0]);
            float2 hy = make_float2(ngx + igx * (hold.x - ngx),
                                    ngy + igy * (hold.y - ngy));
            *reinterpret_cast<float2*>(&hcur[b2i * 512 + j0]) = hy;
            if (layer == 0) {
                *reinterpret_cast<float2*>(&g_y0[((size_t)t * B_ + b2i) * H_ + j0]) = hy;
                if (t == T_ - 1)
                    *reinterpret_cast<float2*>(&hl0[b2i * 512 + j0]) = hy;
            } else {
                *reinterpret_cast<float2*>(&out[((size_t)t * B_ + b2i) * H_ + j0]) = hy;
                if (t == T_ - 1)
                    *reinterpret_cast<float2*>(&hl1[b2i * 512 + j0]) = hy;
            }
        }

        gridbar(2 * (unsigned)s + 2u);
    }
}

// ---------------- launcher ----------------
extern "C" void kernel_launch(void* const* d_in, const int* in_sizes, int n_in,
                              void* d_out, int out_size) {
    (void)in_sizes; (void)n_in;
    const float* x   = (const float*)d_in[0];
    const float* h0  = (const float*)d_in[1];
    const float* Wih = (const float*)d_in[2];
    const float* bih = (const float*)d_in[3];
    const float* Whh = (const float*)d_in[4];
    const float* bhh = (const float*)d_in[5];
    const float* lng = (const float*)d_in[6];
    const float* lnb = (const float*)d_in[7];
    float* out = (float*)d_out;

    const size_t TBH = (size_t)T_ * B_ * H_;
    const size_t LBH = (size_t)2 * B_ * H_;
    bool has_hl = ((size_t)out_size >= TBH + LBH);

    float* hl_dummy = nullptr;
    cudaGetSymbolAddress((void**)&hl_dummy, g_dummy);
    float* hl0 = has_hl ? out + TBH           : hl_dummy;
    float* hl1 = has_hl ? out + TBH + B_ * H_ : hl_dummy;

    cudaFuncSetAttribute(k_fused, cudaFuncAttributeMaxDynamicSharedMemorySize,
                         SM_FUSED);

    k_init<<<NCTA, 256>>>(h0);
    k_fused<<<NCTA, 256, SM_FUSED>>>(
        Whh, Whh + (size_t)G3 * H_,
        Wih, Wih + (size_t)G3 * H_,
        x, bih, bhh, lng, lnb, out, hl0, hl1);
}